// round 14
// baseline (speedup 1.0000x reference)
#include <cuda_runtime.h>
#include <cuda_fp16.h>
#include <cstdint>
#include <math.h>

// Problem dims (fixed)
#define BB 32
#define TT 2048
#define DK 512
#define HH 512
#define MM (BB*TT)   // 65536

// Scan chunking
#define CH 16
#define CL (TT/CH)   // 128
#define NCHAIN (BB*HH)  // 16384

// Scratch
__device__ __align__(16) __half g_z16 [(size_t)MM * HH];  // 64 MB
__device__ __align__(16) __half g_ht16[(size_t)MM * HH];  // 64 MB
__device__ float g_invtau[MM];
__device__ float g_cB [CH * NCHAIN];
__device__ float g_cP [CH * NCHAIN];
__device__ float g_hin[CH * NCHAIN];
__device__ __align__(16) __half g_w16[2 * HH * DK];       // Wz then Wh (fp16)

// ---------------------------------------------------------------------------
// helpers
// ---------------------------------------------------------------------------
__device__ __forceinline__ uint32_t smem_u32(const void* p) {
    uint32_t a;
    asm("{ .reg .u64 t; cvta.to.shared.u64 t, %1; cvt.u32.u64 %0, t; }"
        : "=r"(a) : "l"(p));
    return a;
}
__device__ __forceinline__ uint32_t packh2(float lo, float hi) {
    uint32_t r;
    asm("cvt.rn.f16x2.f32 %0, %1, %2;" : "=r"(r) : "f"(hi), "f"(lo));
    return r;
}
__device__ __forceinline__ void ldsm4(uint32_t (&r)[4], uint32_t addr) {
    asm volatile("ldmatrix.sync.aligned.m8n8.x4.shared.b16 {%0,%1,%2,%3}, [%4];"
        : "=r"(r[0]), "=r"(r[1]), "=r"(r[2]), "=r"(r[3]) : "r"(addr));
}
__device__ __forceinline__ void mma_f16(float (&d)[4], const uint32_t (&a)[4],
                                        uint32_t b0, uint32_t b1) {
    asm volatile(
        "mma.sync.aligned.m16n8k16.row.col.f32.f16.f16.f32 "
        "{%0,%1,%2,%3}, {%4,%5,%6,%7}, {%8,%9}, {%0,%1,%2,%3};"
        : "+f"(d[0]), "+f"(d[1]), "+f"(d[2]), "+f"(d[3])
        : "r"(a[0]), "r"(a[1]), "r"(a[2]), "r"(a[3]), "r"(b0), "r"(b1));
}
__device__ __forceinline__ void cp16(uint32_t saddr, const void* gptr) {
    asm volatile("cp.async.cg.shared.global [%0], [%1], 16;"
                 :: "r"(saddr), "l"(__cvta_generic_to_global(gptr)));
}
#define CP_COMMIT() asm volatile("cp.async.commit_group;" ::: "memory")
#define CP_WAIT2()  asm volatile("cp.async.wait_group 2;" ::: "memory")
#define STS128V(addr, v0, v1, v2, v3)                                         \
    asm volatile("st.shared.v4.b32 [%0], {%1,%2,%3,%4};"                      \
                 :: "r"(addr), "r"(v0), "r"(v1), "r"(v2), "r"(v3) : "memory")

__device__ __forceinline__ float fast_sigmoid(float x) {
    return 1.f / (1.f + __expf(-x));
}

// ---------------------------------------------------------------------------
// Kernel 0a: tau
// ---------------------------------------------------------------------------
__global__ void tau_kernel(const float* __restrict__ motion_mag,
                           const float* __restrict__ w,
                           const float* __restrict__ b,
                           const float* __restrict__ alpha)
{
    int i = blockIdx.x * blockDim.x + threadIdx.x;
    if (i >= MM) return;
    float a  = alpha[0];
    float sp = (a > 20.f) ? a : log1pf(expf(a));
    float t  = w[0] * motion_mag[i] + b[0];
    float s  = fast_sigmoid(t);
    g_invtau[i] = 1.f / (1.f + sp * s);
}

// ---------------------------------------------------------------------------
// Kernel 0b: W fp32 -> fp16 (2 MB, tiny)
// ---------------------------------------------------------------------------
__global__ void cvt_w(const float4* __restrict__ Wz, const float4* __restrict__ Wh)
{
    const int i = blockIdx.x * blockDim.x + threadIdx.x;
    const int half_n = HH * DK / 8;
    const float4* src = (i < half_n) ? Wz : Wh;
    const int j = (i < half_n) ? i : i - half_n;
    float4 a = src[2 * j];
    float4 b = src[2 * j + 1];
    uint4 o;
    o.x = packh2(a.x, a.y); o.y = packh2(a.z, a.w);
    o.z = packh2(b.x, b.y); o.w = packh2(b.z, b.w);
    ((uint4*)g_w16)[i] = o;
}

// ---------------------------------------------------------------------------
// Kernel 2: fused fp16 GEMM (R8 geometry): BM=128 BN=256 BK=64, 512 threads,
//   warp grid 2(m) x 8(n), warp tile 64x32, 4-stage pipeline, one sync/chunk.
//   A path: LDG fp32 from X -> cvt -> STS (no pre-converted g_x16).
//   B path: cp.async fp16 from g_w16 (wait_group tracks B only).
// ---------------------------------------------------------------------------
#define A_BYTES 16384                 // 128 rows x 128B
#define B_BYTES 32768                 // 256 rows x 128B
#define STAGE_BYTES (A_BYTES + B_BYTES)
#define NST 4
#define GEMM_SMEM (NST * STAGE_BYTES) // 196608
#define NCHUNK 8

__global__ __launch_bounds__(512, 1)
void gemm_fused(const float* __restrict__ X,
                const float* __restrict__ bz, const float* __restrict__ bh)
{
    extern __shared__ uint32_t dsm[];
    const uint32_t sb = smem_u32(dsm);

    const int tid  = threadIdx.x;
    const int lane = tid & 31;
    const int wid  = tid >> 5;
    const int warp_m = wid & 1;
    const int warp_n = wid >> 1;

    const bool GATE = (blockIdx.x < 2);
    const __half* W16  = g_w16 + (GATE ? 0 : (size_t)HH * DK);
    const float* bias  = GATE ? bz : bh;
    const int n0 = (blockIdx.x & 1) * 256;
    const int m0 = blockIdx.y * 128;

    // ---- loader mapping ----
    const int lrow = tid >> 3;   // 0..63
    const int lc   = tid & 7;    // 16B-fp16 chunk in 128B row
    const uint32_t asw = (uint32_t)(((lc ^ (lrow & 7)) << 4));

    const float*  Xrow0 = X    + (size_t)(m0 + lrow) * DK + lc * 8;  // 8 fp32
    const __half* Wrow0 = W16  + (size_t)(n0 + lrow) * DK + lc * 8;  // 8 fp16

    // A smem targets (rows lrow and lrow+64; same swizzle since (r+64)&7==r&7)
    const uint32_t a_st0 = (uint32_t)lrow * 128 + asw;
    const uint32_t a_st1 = (uint32_t)(lrow + 64) * 128 + asw;

    // ---- fragment ldmatrix bases (stage-relative) ----
    const int lr15 = lane & 15;
    const int hi   = lane >> 4;
    const int swz  = lane & 7;
    const uint32_t a_rel = (uint32_t)((warp_m * 64 + lr15) * 128);
    const uint32_t b_rel = (uint32_t)(A_BYTES + (warp_n * 32 + lr15) * 128);

    float acc[4][4][4];
    #pragma unroll
    for (int i = 0; i < 4; i++)
        #pragma unroll
        for (int j = 0; j < 4; j++)
            #pragma unroll
            for (int q = 0; q < 4; q++)
                acc[i][j][q] = 0.f;

    // load A chunk (fp32) into registers
    auto lda = [&](int ch, float4 (&v)[4]) {
        const float* p0 = Xrow0 + ch * 64;
        v[0] = ((const float4*)p0)[0];
        v[1] = ((const float4*)p0)[1];
        const float* p1 = p0 + (size_t)64 * DK;
        v[2] = ((const float4*)p1)[0];
        v[3] = ((const float4*)p1)[1];
    };
    // convert + store A chunk into stage s
    auto sts_a = [&](int s, const float4 (&v)[4]) {
        const uint32_t sA = sb + (uint32_t)s * STAGE_BYTES;
        STS128V(sA + a_st0, packh2(v[0].x, v[0].y), packh2(v[0].z, v[0].w),
                            packh2(v[1].x, v[1].y), packh2(v[1].z, v[1].w));
        STS128V(sA + a_st1, packh2(v[2].x, v[2].y), packh2(v[2].z, v[2].w),
                            packh2(v[3].x, v[3].y), packh2(v[3].z, v[3].w));
    };
    // B stage via cp.async
    auto load_b = [&](int ch, int s) {
        const uint32_t sB = sb + (uint32_t)s * STAGE_BYTES + A_BYTES;
        const int koff = ch * 64;
        #pragma unroll
        for (int j = 0; j < 4; j++)
            cp16(sB + (uint32_t)(lrow + 64 * j) * 128 + asw,
                 Wrow0 + (size_t)(64 * j) * DK + koff);
    };

    // prologue: stages 0..2
    #pragma unroll
    for (int s = 0; s < 3; s++) {
        float4 av[4];
        lda(s, av);
        sts_a(s, av);
        load_b(s, s);
        CP_COMMIT();
    }

    for (int ch = 0; ch < NCHUNK; ++ch) {
        CP_WAIT2();          // B stage ch complete (<=2 groups pending)
        __syncthreads();     // A STS visible; all warps done with mma(ch-1)

        const bool pf = (ch + 3 < NCHUNK);
        float4 av[4];
        if (pf) {
            lda(ch + 3, av);          // LDG early; latency hidden by compute
            load_b(ch + 3, (ch + 3) & 3);
        }
        CP_COMMIT();

        const uint32_t sbase = sb + (uint32_t)(ch & 3) * STAGE_BYTES;
        const uint32_t a_base = sbase + a_rel;
        const uint32_t b_base = sbase + b_rel;

        #pragma unroll
        for (int ks = 0; ks < 4; ks++) {
            const uint32_t xoff = (uint32_t)(((ks * 2 + hi) ^ swz) << 4);
            uint32_t af[4][4], bf[2][4];
            #pragma unroll
            for (int mt = 0; mt < 4; mt++)
                ldsm4(af[mt], a_base + mt * 2048 + xoff);
            #pragma unroll
            for (int p = 0; p < 2; p++)
                ldsm4(bf[p], b_base + p * 2048 + xoff);
            #pragma unroll
            for (int mt = 0; mt < 4; mt++) {
                #pragma unroll
                for (int p = 0; p < 2; p++) {
                    mma_f16(acc[mt][2*p+0], af[mt], bf[p][0], bf[p][2]);
                    mma_f16(acc[mt][2*p+1], af[mt], bf[p][1], bf[p][3]);
                }
            }
        }

        if (pf) sts_a((ch + 3) & 3, av);   // stage (ch+3)&3 free since sync(ch)
    }

    // ---- epilogue: fp16 half2 stores ----
    uint32_t* out = (uint32_t*)(GATE ? g_z16 : g_ht16);
    #pragma unroll
    for (int mt = 0; mt < 4; mt++) {
        const int m  = m0 + warp_m * 64 + mt * 16 + (lane >> 2);
        const float it0 = GATE ? g_invtau[m]     : 0.f;
        const float it1 = GATE ? g_invtau[m + 8] : 0.f;
        #pragma unroll
        for (int nt = 0; nt < 4; nt++) {
            const int n = n0 + warp_n * 32 + nt * 8 + (lane & 3) * 2;
            const float bs0 = bias[n];
            const float bs1 = bias[n + 1];
            float v0 = acc[mt][nt][0] + bs0;
            float v1 = acc[mt][nt][1] + bs1;
            float v2 = acc[mt][nt][2] + bs0;
            float v3 = acc[mt][nt][3] + bs1;
            if (GATE) {
                v0 = fast_sigmoid(v0 * it0);
                v1 = fast_sigmoid(v1 * it0);
                v2 = fast_sigmoid(v2 * it1);
                v3 = fast_sigmoid(v3 * it1);
            }
            out[((size_t)m * HH + n) >> 1]       = packh2(v0, v1);
            out[((size_t)(m + 8) * HH + n) >> 1] = packh2(v2, v3);
        }
    }
}

// ---------------------------------------------------------------------------
// Kernel 3a: per-chunk local scan (h_in = 0), fp16 inputs (R8 form)
// ---------------------------------------------------------------------------
__global__ void scan_p1()
{
    const int idx = blockIdx.x * blockDim.x + threadIdx.x;
    const int bh = idx & (NCHAIN - 1);
    const int c  = idx >> 14;           // 0..14
    const int b  = bh >> 9;
    const int h  = bh & 511;
    size_t p = ((size_t)b * TT + (size_t)c * CL) * HH + h;

    float hv = 0.f, P = 1.f;
    #pragma unroll 1
    for (int t = 0; t < CL; t += 8) {
        float z[8], a[8];
        #pragma unroll
        for (int u = 0; u < 8; u++) {
            z[u] = __half2float(g_z16 [p + (size_t)u * HH]);
            a[u] = __half2float(g_ht16[p + (size_t)u * HH]);
        }
        #pragma unroll
        for (int u = 0; u < 8; u++) {
            hv = fmaf(z[u], a[u] - hv, hv);
            P *= (1.f - z[u]);
        }
        p += (size_t)8 * HH;
    }
    g_cB[(size_t)c * NCHAIN + bh] = hv;
    g_cP[(size_t)c * NCHAIN + bh] = P;
}

// ---------------------------------------------------------------------------
// Kernel 3b: compose chunk carries
// ---------------------------------------------------------------------------
__global__ void scan_p2()
{
    const int bh = blockIdx.x * blockDim.x + threadIdx.x;
    float cb[CH - 1], cp[CH - 1];
    #pragma unroll
    for (int c = 0; c < CH - 1; c++) {
        cb[c] = g_cB[(size_t)c * NCHAIN + bh];
        cp[c] = g_cP[(size_t)c * NCHAIN + bh];
    }
    float hv = 0.f;
    #pragma unroll
    for (int c = 0; c < CH; c++) {
        g_hin[(size_t)c * NCHAIN + bh] = hv;
        if (c < CH - 1) hv = fmaf(cp[c], hv, cb[c]);
    }
}

// ---------------------------------------------------------------------------
// Kernel 3c: final per-chunk scan, writes fp32 output (R8 form)
// ---------------------------------------------------------------------------
__global__ void scan_p3(float* __restrict__ out)
{
    const int idx = blockIdx.x * blockDim.x + threadIdx.x;
    const int bh = idx & (NCHAIN - 1);
    const int c  = idx >> 14;           // 0..15
    const int b  = bh >> 9;
    const int h  = bh & 511;
    size_t p = ((size_t)b * TT + (size_t)c * CL) * HH + h;

    float hv = g_hin[(size_t)c * NCHAIN + bh];
    #pragma unroll 1
    for (int t = 0; t < CL; t += 8) {
        float z[8], a[8];
        #pragma unroll
        for (int u = 0; u < 8; u++) {
            z[u] = __half2float(g_z16 [p + (size_t)u * HH]);
            a[u] = __half2float(g_ht16[p + (size_t)u * HH]);
        }
        #pragma unroll
        for (int u = 0; u < 8; u++) {
            hv = fmaf(z[u], a[u] - hv, hv);
            out[p + (size_t)u * HH] = hv;
        }
        p += (size_t)8 * HH;
    }
}

// ---------------------------------------------------------------------------
// Launch
// ---------------------------------------------------------------------------
extern "C" void kernel_launch(void* const* d_in, const int* in_sizes, int n_in,
                              void* d_out, int out_size)
{
    const float* x     = (const float*)d_in[0];
    const float* mmg   = (const float*)d_in[1];
    const float* Wz    = (const float*)d_in[2];
    const float* bz    = (const float*)d_in[3];
    const float* Wh    = (const float*)d_in[4];
    const float* bh    = (const float*)d_in[5];
    const float* mw    = (const float*)d_in[6];
    const float* mb    = (const float*)d_in[7];
    const float* alpha = (const float*)d_in[8];
    float* out         = (float*)d_out;

    cudaFuncSetAttribute(gemm_fused, cudaFuncAttributeMaxDynamicSharedMemorySize,
                         GEMM_SMEM);

    tau_kernel<<<(MM + 255) / 256, 256>>>(mmg, mw, mb, alpha);
    cvt_w<<<(2 * HH * DK / 8) / 256, 256>>>((const float4*)Wz, (const float4*)Wh);

    dim3 grid(4, MM / 128);
    gemm_fused<<<grid, 512, GEMM_SMEM>>>(x, bz, bh);

    scan_p1<<<(15 * NCHAIN) / 256, 256>>>();
    scan_p2<<<NCHAIN / 256, 256>>>();
    scan_p3<<<(CH * NCHAIN) / 256, 256>>>(out);
}

// round 15
// speedup vs baseline: 1.3967x; 1.3967x over previous
#include <cuda_runtime.h>
#include <cuda_fp16.h>
#include <cstdint>
#include <math.h>

// Problem dims (fixed)
#define BB 32
#define TT 2048
#define DK 512
#define HH 512
#define MM (BB*TT)   // 65536

// Scan chunking
#define CH 16
#define CL (TT/CH)   // 128
#define NCHAIN (BB*HH)  // 16384

// Scratch
__device__ __align__(16) __half g_z16 [(size_t)MM * HH];  // 64 MB
__device__ __align__(16) __half g_ht16[(size_t)MM * HH];  // 64 MB
__device__ float g_invtau[MM];
__device__ float g_cB [CH * NCHAIN];
__device__ float g_cP [CH * NCHAIN];
__device__ float g_hin[CH * NCHAIN];
__device__ __align__(16) __half g_x16[(size_t)MM * DK];   // 64 MB
__device__ __align__(16) __half g_w16[2 * HH * DK];       // Wz then Wh

// ---------------------------------------------------------------------------
// helpers
// ---------------------------------------------------------------------------
__device__ __forceinline__ uint32_t smem_u32(const void* p) {
    uint32_t a;
    asm("{ .reg .u64 t; cvta.to.shared.u64 t, %1; cvt.u32.u64 %0, t; }"
        : "=r"(a) : "l"(p));
    return a;
}
__device__ __forceinline__ uint32_t packh2(float lo, float hi) {
    uint32_t r;
    asm("cvt.rn.f16x2.f32 %0, %1, %2;" : "=r"(r) : "f"(hi), "f"(lo));
    return r;
}
__device__ __forceinline__ void ldsm4(uint32_t (&r)[4], uint32_t addr) {
    asm volatile("ldmatrix.sync.aligned.m8n8.x4.shared.b16 {%0,%1,%2,%3}, [%4];"
        : "=r"(r[0]), "=r"(r[1]), "=r"(r[2]), "=r"(r[3]) : "r"(addr));
}
__device__ __forceinline__ void mma_f16(float (&d)[4], const uint32_t (&a)[4],
                                        uint32_t b0, uint32_t b1) {
    asm volatile(
        "mma.sync.aligned.m16n8k16.row.col.f32.f16.f16.f32 "
        "{%0,%1,%2,%3}, {%4,%5,%6,%7}, {%8,%9}, {%0,%1,%2,%3};"
        : "+f"(d[0]), "+f"(d[1]), "+f"(d[2]), "+f"(d[3])
        : "r"(a[0]), "r"(a[1]), "r"(a[2]), "r"(a[3]), "r"(b0), "r"(b1));
}
__device__ __forceinline__ void cp16(uint32_t saddr, const void* gptr) {
    asm volatile("cp.async.cg.shared.global [%0], [%1], 16;"
                 :: "r"(saddr), "l"(__cvta_generic_to_global(gptr)));
}
#define CP_COMMIT() asm volatile("cp.async.commit_group;" ::: "memory")
#define CP_WAIT2()  asm volatile("cp.async.wait_group 2;" ::: "memory")

// ---------------------------------------------------------------------------
// Kernel 0a: tau
// ---------------------------------------------------------------------------
__global__ void tau_kernel(const float* __restrict__ motion_mag,
                           const float* __restrict__ w,
                           const float* __restrict__ b,
                           const float* __restrict__ alpha)
{
    int i = blockIdx.x * blockDim.x + threadIdx.x;
    if (i >= MM) return;
    float a  = alpha[0];
    float sp = (a > 20.f) ? a : log1pf(expf(a));
    float t  = w[0] * motion_mag[i] + b[0];
    float s  = 1.f / (1.f + expf(-t));
    g_invtau[i] = 1.f / (1.f + sp * s);
}

// ---------------------------------------------------------------------------
// Kernel 0b/0c: fp32 -> fp16 conversion
// ---------------------------------------------------------------------------
__global__ void cvt_x(const float4* __restrict__ X)
{
    const int i = blockIdx.x * blockDim.x + threadIdx.x;
    float4 a = X[2 * i];
    float4 b = X[2 * i + 1];
    uint4 o;
    o.x = packh2(a.x, a.y); o.y = packh2(a.z, a.w);
    o.z = packh2(b.x, b.y); o.w = packh2(b.z, b.w);
    ((uint4*)g_x16)[i] = o;
}
__global__ void cvt_w(const float4* __restrict__ Wz, const float4* __restrict__ Wh)
{
    const int i = blockIdx.x * blockDim.x + threadIdx.x;
    const int half_n = HH * DK / 8;
    const float4* src = (i < half_n) ? Wz : Wh;
    const int j = (i < half_n) ? i : i - half_n;
    float4 a = src[2 * j];
    float4 b = src[2 * j + 1];
    uint4 o;
    o.x = packh2(a.x, a.y); o.y = packh2(a.z, a.w);
    o.z = packh2(b.x, b.y); o.w = packh2(b.z, b.w);
    ((uint4*)g_w16)[i] = o;
}

// ---------------------------------------------------------------------------
// Kernel 2: fused fp16 GEMM (R8 geometry): BM=128 BN=256 BK=64, 512 threads,
//   4-stage cp.async pipeline, ONE __syncthreads per chunk.
//   grid (4, 512): x = {z|n0=0, z|n0=256, h|n0=0, h|n0=256}; y = m-tile.
//   Epilogue stores fp16 (half2) to g_z16 / g_ht16.
// ---------------------------------------------------------------------------
#define A_BYTES 16384                 // 128 rows x 128B
#define B_BYTES 32768                 // 256 rows x 128B
#define STAGE_BYTES (A_BYTES + B_BYTES)
#define NST 4
#define GEMM_SMEM (NST * STAGE_BYTES) // 196608
#define NCHUNK 8

__global__ __launch_bounds__(512, 1)
void gemm_fused(const float* __restrict__ bz, const float* __restrict__ bh)
{
    extern __shared__ uint32_t dsm[];
    const uint32_t sb = smem_u32(dsm);

    const int tid  = threadIdx.x;
    const int lane = tid & 31;
    const int wid  = tid >> 5;
    const int warp_m = wid & 1;
    const int warp_n = wid >> 1;

    const bool GATE = (blockIdx.x < 2);
    const __half* W16  = g_w16 + (GATE ? 0 : (size_t)HH * DK);
    const float* bias  = GATE ? bz : bh;
    const int n0 = (blockIdx.x & 1) * 256;
    const int m0 = blockIdx.y * 128;

    // ---- cp.async loader mapping ----
    const int lrow = tid >> 3;   // 0..63
    const int lc   = tid & 7;    // 16B chunk in 128B row
    const uint32_t asw = (uint32_t)(((lc ^ (lrow & 7)) << 4));

    const __half* Xrow0 = g_x16 + (size_t)(m0 + lrow) * DK + lc * 8;
    const __half* Wrow0 = W16  + (size_t)(n0 + lrow) * DK + lc * 8;

    // ---- fragment ldmatrix bases (stage-relative) ----
    const int lr15 = lane & 15;
    const int hi   = lane >> 4;
    const int swz  = lane & 7;
    const uint32_t a_rel = (uint32_t)((warp_m * 64 + lr15) * 128);
    const uint32_t b_rel = (uint32_t)(A_BYTES + (warp_n * 32 + lr15) * 128);

    float acc[4][4][4];
    #pragma unroll
    for (int i = 0; i < 4; i++)
        #pragma unroll
        for (int j = 0; j < 4; j++)
            #pragma unroll
            for (int q = 0; q < 4; q++)
                acc[i][j][q] = 0.f;

    auto load_stage = [&](int ch, int s) {
        const uint32_t sA = sb + (uint32_t)s * STAGE_BYTES;
        const uint32_t sB = sA + A_BYTES;
        const int koff = ch * 64;   // fp16 elements
        #pragma unroll
        for (int j = 0; j < 2; j++)
            cp16(sA + (uint32_t)(lrow + 64 * j) * 128 + asw,
                 Xrow0 + (size_t)(64 * j) * DK + koff);
        #pragma unroll
        for (int j = 0; j < 4; j++)
            cp16(sB + (uint32_t)(lrow + 64 * j) * 128 + asw,
                 Wrow0 + (size_t)(64 * j) * DK + koff);
    };

    // prologue: stages 0..2
    #pragma unroll
    for (int s = 0; s < 3; s++) { load_stage(s, s); CP_COMMIT(); }

    for (int ch = 0; ch < NCHUNK; ++ch) {
        CP_WAIT2();          // stage ch complete (<=2 groups pending)
        __syncthreads();     // data visible; all warps done with mma(ch-1)

        if (ch + 3 < NCHUNK) load_stage(ch + 3, (ch + 3) & 3);
        CP_COMMIT();

        const uint32_t sbase = sb + (uint32_t)(ch & 3) * STAGE_BYTES;
        const uint32_t a_base = sbase + a_rel;
        const uint32_t b_base = sbase + b_rel;

        #pragma unroll
        for (int ks = 0; ks < 4; ks++) {
            const uint32_t xoff = (uint32_t)(((ks * 2 + hi) ^ swz) << 4);
            uint32_t af[4][4], bf[2][4];
            #pragma unroll
            for (int mt = 0; mt < 4; mt++)
                ldsm4(af[mt], a_base + mt * 2048 + xoff);
            #pragma unroll
            for (int p = 0; p < 2; p++)
                ldsm4(bf[p], b_base + p * 2048 + xoff);
            #pragma unroll
            for (int mt = 0; mt < 4; mt++) {
                #pragma unroll
                for (int p = 0; p < 2; p++) {
                    mma_f16(acc[mt][2*p+0], af[mt], bf[p][0], bf[p][2]);
                    mma_f16(acc[mt][2*p+1], af[mt], bf[p][1], bf[p][3]);
                }
            }
        }
    }

    // ---- epilogue: fp16 half2 stores ----
    uint32_t* out = (uint32_t*)(GATE ? g_z16 : g_ht16);
    #pragma unroll
    for (int mt = 0; mt < 4; mt++) {
        const int m  = m0 + warp_m * 64 + mt * 16 + (lane >> 2);
        const float it0 = GATE ? g_invtau[m]     : 0.f;
        const float it1 = GATE ? g_invtau[m + 8] : 0.f;
        #pragma unroll
        for (int nt = 0; nt < 4; nt++) {
            const int n = n0 + warp_n * 32 + nt * 8 + (lane & 3) * 2;
            const float bs0 = bias[n];
            const float bs1 = bias[n + 1];
            float v0 = acc[mt][nt][0] + bs0;
            float v1 = acc[mt][nt][1] + bs1;
            float v2 = acc[mt][nt][2] + bs0;
            float v3 = acc[mt][nt][3] + bs1;
            if (GATE) {
                v0 = 1.f / (1.f + expf(-v0 * it0));
                v1 = 1.f / (1.f + expf(-v1 * it0));
                v2 = 1.f / (1.f + expf(-v2 * it1));
                v3 = 1.f / (1.f + expf(-v3 * it1));
            }
            out[((size_t)m * HH + n) >> 1]       = packh2(v0, v1);
            out[((size_t)(m + 8) * HH + n) >> 1] = packh2(v2, v3);
        }
    }
}

// ---------------------------------------------------------------------------
// Kernel 3a: per-chunk local scan (h_in = 0), fp16 inputs
// ---------------------------------------------------------------------------
__global__ void scan_p1()
{
    const int idx = blockIdx.x * blockDim.x + threadIdx.x;
    const int bh = idx & (NCHAIN - 1);
    const int c  = idx >> 14;           // 0..14
    const int b  = bh >> 9;
    const int h  = bh & 511;
    size_t p = ((size_t)b * TT + (size_t)c * CL) * HH + h;

    float hv = 0.f, P = 1.f;
    #pragma unroll 1
    for (int t = 0; t < CL; t += 8) {
        float z[8], a[8];
        #pragma unroll
        for (int u = 0; u < 8; u++) {
            z[u] = __half2float(g_z16 [p + (size_t)u * HH]);
            a[u] = __half2float(g_ht16[p + (size_t)u * HH]);
        }
        #pragma unroll
        for (int u = 0; u < 8; u++) {
            hv = fmaf(z[u], a[u] - hv, hv);
            P *= (1.f - z[u]);
        }
        p += (size_t)8 * HH;
    }
    g_cB[(size_t)c * NCHAIN + bh] = hv;
    g_cP[(size_t)c * NCHAIN + bh] = P;
}

// ---------------------------------------------------------------------------
// Kernel 3b: compose chunk carries
// ---------------------------------------------------------------------------
__global__ void scan_p2()
{
    const int bh = blockIdx.x * blockDim.x + threadIdx.x;
    float cb[CH - 1], cp[CH - 1];
    #pragma unroll
    for (int c = 0; c < CH - 1; c++) {
        cb[c] = g_cB[(size_t)c * NCHAIN + bh];
        cp[c] = g_cP[(size_t)c * NCHAIN + bh];
    }
    float hv = 0.f;
    #pragma unroll
    for (int c = 0; c < CH; c++) {
        g_hin[(size_t)c * NCHAIN + bh] = hv;
        if (c < CH - 1) hv = fmaf(cp[c], hv, cb[c]);
    }
}

// ---------------------------------------------------------------------------
// Kernel 3c: final per-chunk scan, writes fp32 output
// ---------------------------------------------------------------------------
__global__ void scan_p3(float* __restrict__ out)
{
    const int idx = blockIdx.x * blockDim.x + threadIdx.x;
    const int bh = idx & (NCHAIN - 1);
    const int c  = idx >> 14;           // 0..15
    const int b  = bh >> 9;
    const int h  = bh & 511;
    size_t p = ((size_t)b * TT + (size_t)c * CL) * HH + h;

    float hv = g_hin[(size_t)c * NCHAIN + bh];
    #pragma unroll 1
    for (int t = 0; t < CL; t += 8) {
        float z[8], a[8];
        #pragma unroll
        for (int u = 0; u < 8; u++) {
            z[u] = __half2float(g_z16 [p + (size_t)u * HH]);
            a[u] = __half2float(g_ht16[p + (size_t)u * HH]);
        }
        #pragma unroll
        for (int u = 0; u < 8; u++) {
            hv = fmaf(z[u], a[u] - hv, hv);
            out[p + (size_t)u * HH] = hv;
        }
        p += (size_t)8 * HH;
    }
}

// ---------------------------------------------------------------------------
// Launch
// ---------------------------------------------------------------------------
extern "C" void kernel_launch(void* const* d_in, const int* in_sizes, int n_in,
                              void* d_out, int out_size)
{
    const float* x     = (const float*)d_in[0];
    const float* mmg   = (const float*)d_in[1];
    const float* Wz    = (const float*)d_in[2];
    const float* bz    = (const float*)d_in[3];
    const float* Wh    = (const float*)d_in[4];
    const float* bh    = (const float*)d_in[5];
    const float* mw    = (const float*)d_in[6];
    const float* mb    = (const float*)d_in[7];
    const float* alpha = (const float*)d_in[8];
    float* out         = (float*)d_out;

    cudaFuncSetAttribute(gemm_fused, cudaFuncAttributeMaxDynamicSharedMemorySize,
                         GEMM_SMEM);

    tau_kernel<<<(MM + 255) / 256, 256>>>(mmg, mw, mb, alpha);
    cvt_x<<<(MM * DK / 8) / 256, 256>>>((const float4*)x);
    cvt_w<<<(2 * HH * DK / 8) / 256, 256>>>((const float4*)Wz, (const float4*)Wh);

    dim3 grid(4, MM / 128);
    gemm_fused<<<grid, 512, GEMM_SMEM>>>(bz, bh);

    scan_p1<<<(15 * NCHAIN) / 256, 256>>>();
    scan_p2<<<NCHAIN / 256, 256>>>();
    scan_p3<<<(CH * NCHAIN) / 256, 256>>>(out);
}

// round 16
// speedup vs baseline: 1.4774x; 1.0578x over previous
#include <cuda_runtime.h>
#include <cuda_fp16.h>
#include <cstdint>
#include <math.h>

// Problem dims (fixed)
#define BB 32
#define TT 2048
#define DK 512
#define HH 512
#define MM (BB*TT)   // 65536

// Scan chunking
#define CH 16
#define CL (TT/CH)   // 128
#define NCHAIN (BB*HH)  // 16384
#define NPAIR (NCHAIN/2) // 8192

// Scratch
__device__ __align__(16) __half g_z16 [(size_t)MM * HH];  // 64 MB
__device__ __align__(16) __half g_ht16[(size_t)MM * HH];  // 64 MB
__device__ float g_invtau[MM];
__device__ float g_cB [CH * NCHAIN];
__device__ float g_cP [CH * NCHAIN];
__device__ float g_hin[CH * NCHAIN];
__device__ __align__(16) __half g_x16[(size_t)MM * DK];   // 64 MB
__device__ __align__(16) __half g_w16[2 * HH * DK];       // Wz then Wh

// ---------------------------------------------------------------------------
// helpers
// ---------------------------------------------------------------------------
__device__ __forceinline__ uint32_t smem_u32(const void* p) {
    uint32_t a;
    asm("{ .reg .u64 t; cvta.to.shared.u64 t, %1; cvt.u32.u64 %0, t; }"
        : "=r"(a) : "l"(p));
    return a;
}
__device__ __forceinline__ uint32_t packh2(float lo, float hi) {
    uint32_t r;
    asm("cvt.rn.f16x2.f32 %0, %1, %2;" : "=r"(r) : "f"(hi), "f"(lo));
    return r;
}
__device__ __forceinline__ void ldsm4(uint32_t (&r)[4], uint32_t addr) {
    asm volatile("ldmatrix.sync.aligned.m8n8.x4.shared.b16 {%0,%1,%2,%3}, [%4];"
        : "=r"(r[0]), "=r"(r[1]), "=r"(r[2]), "=r"(r[3]) : "r"(addr));
}
__device__ __forceinline__ void mma_f16(float (&d)[4], const uint32_t (&a)[4],
                                        uint32_t b0, uint32_t b1) {
    asm volatile(
        "mma.sync.aligned.m16n8k16.row.col.f32.f16.f16.f32 "
        "{%0,%1,%2,%3}, {%4,%5,%6,%7}, {%8,%9}, {%0,%1,%2,%3};"
        : "+f"(d[0]), "+f"(d[1]), "+f"(d[2]), "+f"(d[3])
        : "r"(a[0]), "r"(a[1]), "r"(a[2]), "r"(a[3]), "r"(b0), "r"(b1));
}
__device__ __forceinline__ void cp16(uint32_t saddr, const void* gptr) {
    asm volatile("cp.async.cg.shared.global [%0], [%1], 16;"
                 :: "r"(saddr), "l"(__cvta_generic_to_global(gptr)));
}
#define CP_COMMIT() asm volatile("cp.async.commit_group;" ::: "memory")
#define CP_WAIT2()  asm volatile("cp.async.wait_group 2;" ::: "memory")

// ---------------------------------------------------------------------------
// Kernel 0: fused prep — cvt_x (blocks [0,16384)), cvt_w ([16384,16640)),
//   tau ([16640,16896))
// ---------------------------------------------------------------------------
#define PREP_X_BLKS (MM * DK / 8 / 256)        // 16384
#define PREP_W_BLKS (2 * HH * DK / 8 / 256)    // 256
#define PREP_T_BLKS (MM / 256)                 // 256
#define PREP_BLKS (PREP_X_BLKS + PREP_W_BLKS + PREP_T_BLKS)

__global__ void prep_kernel(const float4* __restrict__ X,
                            const float4* __restrict__ Wz,
                            const float4* __restrict__ Wh,
                            const float* __restrict__ motion_mag,
                            const float* __restrict__ mw,
                            const float* __restrict__ mb,
                            const float* __restrict__ alpha)
{
    const int blk = blockIdx.x;
    if (blk < PREP_X_BLKS) {
        const int i = blk * blockDim.x + threadIdx.x;
        float4 a = X[2 * i];
        float4 b = X[2 * i + 1];
        uint4 o;
        o.x = packh2(a.x, a.y); o.y = packh2(a.z, a.w);
        o.z = packh2(b.x, b.y); o.w = packh2(b.z, b.w);
        ((uint4*)g_x16)[i] = o;
    } else if (blk < PREP_X_BLKS + PREP_W_BLKS) {
        const int i = (blk - PREP_X_BLKS) * blockDim.x + threadIdx.x;
        const int half_n = HH * DK / 8;
        const float4* src = (i < half_n) ? Wz : Wh;
        const int j = (i < half_n) ? i : i - half_n;
        float4 a = src[2 * j];
        float4 b = src[2 * j + 1];
        uint4 o;
        o.x = packh2(a.x, a.y); o.y = packh2(a.z, a.w);
        o.z = packh2(b.x, b.y); o.w = packh2(b.z, b.w);
        ((uint4*)g_w16)[i] = o;
    } else {
        const int i = (blk - PREP_X_BLKS - PREP_W_BLKS) * blockDim.x + threadIdx.x;
        float a  = alpha[0];
        float sp = (a > 20.f) ? a : log1pf(expf(a));
        float t  = mw[0] * motion_mag[i] + mb[0];
        float s  = 1.f / (1.f + expf(-t));
        g_invtau[i] = 1.f / (1.f + sp * s);
    }
}

// ---------------------------------------------------------------------------
// Kernel 2: fused fp16 GEMM (R8 geometry, UNCHANGED): BM=128 BN=256 BK=64,
//   512 threads, 4-stage cp.async pipeline, one __syncthreads per chunk.
// ---------------------------------------------------------------------------
#define A_BYTES 16384                 // 128 rows x 128B
#define B_BYTES 32768                 // 256 rows x 128B
#define STAGE_BYTES (A_BYTES + B_BYTES)
#define NST 4
#define GEMM_SMEM (NST * STAGE_BYTES) // 196608
#define NCHUNK 8

__global__ __launch_bounds__(512, 1)
void gemm_fused(const float* __restrict__ bz, const float* __restrict__ bh)
{
    extern __shared__ uint32_t dsm[];
    const uint32_t sb = smem_u32(dsm);

    const int tid  = threadIdx.x;
    const int lane = tid & 31;
    const int wid  = tid >> 5;
    const int warp_m = wid & 1;
    const int warp_n = wid >> 1;

    const bool GATE = (blockIdx.x < 2);
    const __half* W16  = g_w16 + (GATE ? 0 : (size_t)HH * DK);
    const float* bias  = GATE ? bz : bh;
    const int n0 = (blockIdx.x & 1) * 256;
    const int m0 = blockIdx.y * 128;

    const int lrow = tid >> 3;   // 0..63
    const int lc   = tid & 7;    // 16B chunk in 128B row
    const uint32_t asw = (uint32_t)(((lc ^ (lrow & 7)) << 4));

    const __half* Xrow0 = g_x16 + (size_t)(m0 + lrow) * DK + lc * 8;
    const __half* Wrow0 = W16  + (size_t)(n0 + lrow) * DK + lc * 8;

    const int lr15 = lane & 15;
    const int hi   = lane >> 4;
    const int swz  = lane & 7;
    const uint32_t a_rel = (uint32_t)((warp_m * 64 + lr15) * 128);
    const uint32_t b_rel = (uint32_t)(A_BYTES + (warp_n * 32 + lr15) * 128);

    float acc[4][4][4];
    #pragma unroll
    for (int i = 0; i < 4; i++)
        #pragma unroll
        for (int j = 0; j < 4; j++)
            #pragma unroll
            for (int q = 0; q < 4; q++)
                acc[i][j][q] = 0.f;

    auto load_stage = [&](int ch, int s) {
        const uint32_t sA = sb + (uint32_t)s * STAGE_BYTES;
        const uint32_t sB = sA + A_BYTES;
        const int koff = ch * 64;   // fp16 elements
        #pragma unroll
        for (int j = 0; j < 2; j++)
            cp16(sA + (uint32_t)(lrow + 64 * j) * 128 + asw,
                 Xrow0 + (size_t)(64 * j) * DK + koff);
        #pragma unroll
        for (int j = 0; j < 4; j++)
            cp16(sB + (uint32_t)(lrow + 64 * j) * 128 + asw,
                 Wrow0 + (size_t)(64 * j) * DK + koff);
    };

    #pragma unroll
    for (int s = 0; s < 3; s++) { load_stage(s, s); CP_COMMIT(); }

    for (int ch = 0; ch < NCHUNK; ++ch) {
        CP_WAIT2();
        __syncthreads();

        if (ch + 3 < NCHUNK) load_stage(ch + 3, (ch + 3) & 3);
        CP_COMMIT();

        const uint32_t sbase = sb + (uint32_t)(ch & 3) * STAGE_BYTES;
        const uint32_t a_base = sbase + a_rel;
        const uint32_t b_base = sbase + b_rel;

        #pragma unroll
        for (int ks = 0; ks < 4; ks++) {
            const uint32_t xoff = (uint32_t)(((ks * 2 + hi) ^ swz) << 4);
            uint32_t af[4][4], bf[2][4];
            #pragma unroll
            for (int mt = 0; mt < 4; mt++)
                ldsm4(af[mt], a_base + mt * 2048 + xoff);
            #pragma unroll
            for (int p = 0; p < 2; p++)
                ldsm4(bf[p], b_base + p * 2048 + xoff);
            #pragma unroll
            for (int mt = 0; mt < 4; mt++) {
                #pragma unroll
                for (int p = 0; p < 2; p++) {
                    mma_f16(acc[mt][2*p+0], af[mt], bf[p][0], bf[p][2]);
                    mma_f16(acc[mt][2*p+1], af[mt], bf[p][1], bf[p][3]);
                }
            }
        }
    }

    // ---- epilogue: fp16 half2 stores ----
    uint32_t* out = (uint32_t*)(GATE ? g_z16 : g_ht16);
    #pragma unroll
    for (int mt = 0; mt < 4; mt++) {
        const int m  = m0 + warp_m * 64 + mt * 16 + (lane >> 2);
        const float it0 = GATE ? g_invtau[m]     : 0.f;
        const float it1 = GATE ? g_invtau[m + 8] : 0.f;
        #pragma unroll
        for (int nt = 0; nt < 4; nt++) {
            const int n = n0 + warp_n * 32 + nt * 8 + (lane & 3) * 2;
            const float bs0 = bias[n];
            const float bs1 = bias[n + 1];
            float v0 = acc[mt][nt][0] + bs0;
            float v1 = acc[mt][nt][1] + bs1;
            float v2 = acc[mt][nt][2] + bs0;
            float v3 = acc[mt][nt][3] + bs1;
            if (GATE) {
                v0 = 1.f / (1.f + expf(-v0 * it0));
                v1 = 1.f / (1.f + expf(-v1 * it0));
                v2 = 1.f / (1.f + expf(-v2 * it1));
                v3 = 1.f / (1.f + expf(-v3 * it1));
            }
            out[((size_t)m * HH + n) >> 1]       = packh2(v0, v1);
            out[((size_t)(m + 8) * HH + n) >> 1] = packh2(v2, v3);
        }
    }
}

// ---------------------------------------------------------------------------
// Kernel 3a: per-chunk local scan (h_in = 0), 2 chains/thread via half2
// ---------------------------------------------------------------------------
__global__ void scan_p1()
{
    const int idx = blockIdx.x * blockDim.x + threadIdx.x; // 0 .. 15*8192-1
    const int q  = idx & (NPAIR - 1);   // chain pair
    const int c  = idx >> 13;           // 0..14
    const int bh = q * 2;
    const int b  = bh >> 9;
    const int h  = bh & 511;
    size_t p = (((size_t)b * TT + (size_t)c * CL) * HH + h) >> 1; // half2 index

    const __half2* zz = (const __half2*)g_z16;
    const __half2* aa = (const __half2*)g_ht16;
    const size_t step = HH / 2;

    float hv0 = 0.f, hv1 = 0.f, P0 = 1.f, P1 = 1.f;
    #pragma unroll 1
    for (int t = 0; t < CL; t += 8) {
        float2 z[8], a[8];
        #pragma unroll
        for (int u = 0; u < 8; u++) {
            z[u] = __half22float2(zz[p + (size_t)u * step]);
            a[u] = __half22float2(aa[p + (size_t)u * step]);
        }
        #pragma unroll
        for (int u = 0; u < 8; u++) {
            hv0 = fmaf(z[u].x, a[u].x - hv0, hv0); P0 *= (1.f - z[u].x);
            hv1 = fmaf(z[u].y, a[u].y - hv1, hv1); P1 *= (1.f - z[u].y);
        }
        p += (size_t)8 * step;
    }
    *(float2*)(g_cB + (size_t)c * NCHAIN + bh) = make_float2(hv0, hv1);
    *(float2*)(g_cP + (size_t)c * NCHAIN + bh) = make_float2(P0,  P1);
}

// ---------------------------------------------------------------------------
// Kernel 3b: compose chunk carries
// ---------------------------------------------------------------------------
__global__ void scan_p2()
{
    const int bh = blockIdx.x * blockDim.x + threadIdx.x;
    float cb[CH - 1], cp[CH - 1];
    #pragma unroll
    for (int c = 0; c < CH - 1; c++) {
        cb[c] = g_cB[(size_t)c * NCHAIN + bh];
        cp[c] = g_cP[(size_t)c * NCHAIN + bh];
    }
    float hv = 0.f;
    #pragma unroll
    for (int c = 0; c < CH; c++) {
        g_hin[(size_t)c * NCHAIN + bh] = hv;
        if (c < CH - 1) hv = fmaf(cp[c], hv, cb[c]);
    }
}

// ---------------------------------------------------------------------------
// Kernel 3c: final per-chunk scan, 2 chains/thread, fp32 float2 output
// ---------------------------------------------------------------------------
__global__ void scan_p3(float* __restrict__ out)
{
    const int idx = blockIdx.x * blockDim.x + threadIdx.x; // 0 .. 16*8192-1
    const int q  = idx & (NPAIR - 1);
    const int c  = idx >> 13;           // 0..15
    const int bh = q * 2;
    const int b  = bh >> 9;
    const int h  = bh & 511;
    const size_t base = ((size_t)b * TT + (size_t)c * CL) * HH + h;
    size_t p = base >> 1;               // half2 index

    const __half2* zz = (const __half2*)g_z16;
    const __half2* aa = (const __half2*)g_ht16;
    const size_t step = HH / 2;

    float2 hq = *(const float2*)(g_hin + (size_t)c * NCHAIN + bh);
    float hv0 = hq.x, hv1 = hq.y;
    float2* po = (float2*)(out + base);
    #pragma unroll 1
    for (int t = 0; t < CL; t += 8) {
        float2 z[8], a[8];
        #pragma unroll
        for (int u = 0; u < 8; u++) {
            z[u] = __half22float2(zz[p + (size_t)u * step]);
            a[u] = __half22float2(aa[p + (size_t)u * step]);
        }
        #pragma unroll
        for (int u = 0; u < 8; u++) {
            hv0 = fmaf(z[u].x, a[u].x - hv0, hv0);
            hv1 = fmaf(z[u].y, a[u].y - hv1, hv1);
            po[(size_t)u * step] = make_float2(hv0, hv1);
        }
        p  += (size_t)8 * step;
        po += (size_t)8 * step;
    }
}

// ---------------------------------------------------------------------------
// Launch
// ---------------------------------------------------------------------------
extern "C" void kernel_launch(void* const* d_in, const int* in_sizes, int n_in,
                              void* d_out, int out_size)
{
    const float* x     = (const float*)d_in[0];
    const float* mmg   = (const float*)d_in[1];
    const float* Wz    = (const float*)d_in[2];
    const float* bz    = (const float*)d_in[3];
    const float* Wh    = (const float*)d_in[4];
    const float* bh    = (const float*)d_in[5];
    const float* mw    = (const float*)d_in[6];
    const float* mb    = (const float*)d_in[7];
    const float* alpha = (const float*)d_in[8];
    float* out         = (float*)d_out;

    cudaFuncSetAttribute(gemm_fused, cudaFuncAttributeMaxDynamicSharedMemorySize,
                         GEMM_SMEM);

    prep_kernel<<<PREP_BLKS, 256>>>((const float4*)x, (const float4*)Wz,
                                    (const float4*)Wh, mmg, mw, mb, alpha);

    dim3 grid(4, MM / 128);
    gemm_fused<<<grid, 512, GEMM_SMEM>>>(bz, bh);

    scan_p1<<<(15 * NPAIR) / 256, 256>>>();
    scan_p2<<<NCHAIN / 256, 256>>>();
    scan_p3<<<(CH * NPAIR) / 256, 256>>>(out);
}